// round 11
// baseline (speedup 1.0000x reference)
#include <cuda_runtime.h>
#include <cuda_fp16.h>
#include <math.h>
#include <stdint.h>

#define BB 64
#define TT 4096
#define DD 256
#define UU 256
#define NTILES 2048          // (BB*TT)/128
#define NSM 152

// ---------------- device-global scratch (allocation-free rule) -------------
__device__ float g_scores[BB * TT];
__device__ float g_cpart[16 * BB * DD];
__device__ __align__(16) __half g_WT[UU * DD];        // (W1+W2)^T fp16, [n][k]
__device__ __align__(16) __half g_Xh[(size_t)BB * TT * DD];  // fp16 shadow of X

// ---------------- smem layout for score kernel -----------------------------
#define KC      64           // k per A chunk
#define WROWB   528          // W row: 512B data + 16B pad
#define AROWB   144          // A row: 128B data + 16B pad
#define W_OFF   0            // 256 rows * 528B = 135168
#define A_OFF   135168       // 2 stages * 128 rows * 144B = 36864
#define ABUF    18432
#define RED_OFF 172032       // 128 rows * 8 warps * 4B = 4096
#define SV_OFF  176128       // 256 floats
#define SM_TOTAL 177152

// ---------------- PTX helpers (plain sm_103-legal: no 'a' features) --------
__device__ __forceinline__ uint32_t smem_u32(const void* p) {
    uint32_t a;
    asm("{ .reg .u64 t; cvta.to.shared.u64 t, %1; cvt.u32.u64 %0, t; }"
        : "=r"(a) : "l"(p));
    return a;
}
__device__ __forceinline__ void ldm4(uint32_t* r, uint32_t addr) {
    asm volatile("ldmatrix.sync.aligned.m8n8.x4.shared.b16 {%0,%1,%2,%3}, [%4];"
                 : "=r"(r[0]), "=r"(r[1]), "=r"(r[2]), "=r"(r[3]) : "r"(addr));
}
__device__ __forceinline__ void mma16816(float* c, const uint32_t* a, const uint32_t* b) {
    asm volatile(
        "mma.sync.aligned.m16n8k16.row.col.f32.f16.f16.f32 "
        "{%0,%1,%2,%3},{%4,%5,%6,%7},{%8,%9},{%0,%1,%2,%3};"
        : "+f"(c[0]), "+f"(c[1]), "+f"(c[2]), "+f"(c[3])
        : "r"(a[0]), "r"(a[1]), "r"(a[2]), "r"(a[3]), "r"(b[0]), "r"(b[1]));
}
__device__ __forceinline__ void cpa16(uint32_t dst, const void* src) {
    asm volatile("cp.async.ca.shared.global [%0], [%1], 16;" :: "r"(dst), "l"(src));
}
#define CP_COMMIT() asm volatile("cp.async.commit_group;" ::: "memory")
#define CP_WAIT0()  asm volatile("cp.async.wait_group 0;" ::: "memory")

__device__ __forceinline__ uint32_t pack_h2(float a, float b) {
    __half2 t = __floats2half2_rn(a, b);
    return *(uint32_t*)&t;
}
__device__ __forceinline__ float fast_tanh(float q) {
    float e = __expf(2.f * q);
    return 1.f - __fdividef(2.f, e + 1.f);   // exact limits at +/-inf
}

// ---------------- phase 0: fuse + transpose weights (fp16) -----------------
__global__ void prep_w(const float* __restrict__ W1, const float* __restrict__ W2)
{
    int idx = blockIdx.x * 256 + threadIdx.x;   // idx = k*256 + u
    int k = idx >> 8, u = idx & 255;
    g_WT[u * DD + k] = __float2half_rn(W1[idx] + W2[idx]);
}

// ---------------- phase 1: persistent HMMA GEMM + tanh/v epilogue ----------
// 152 persistent CTAs x 512 threads. W (256x256 fp16) resident in smem.
// Pipelined A staging; fp16 X shadow written to g_Xh alongside (for ctx pass).
__global__ void __launch_bounds__(512, 1)
score_mma_kernel(const float* __restrict__ X, const float* __restrict__ v)
{
    extern __shared__ char smem[];
    const uint32_t sb = smem_u32(smem);
    const int tid  = threadIdx.x;
    const int wid  = tid >> 5, lane = tid & 31;
    const int wg   = wid >> 3, wn = wid & 7;

    // ---- prologue: W resident load (once) + v
    {
#pragma unroll
        for (int i = 0; i < 16; i++) {
            int u = tid + i * 512;              // 8192 16B-units
            int row = u >> 5, c16 = u & 31;
            cpa16(sb + W_OFF + row * WROWB + c16 * 16,
                  (const char*)(g_WT + (size_t)row * DD) + c16 * 16);
        }
        CP_COMMIT();
    }
    if (tid < 256) ((float*)(smem + SV_OFF))[tid] = v[tid];

    // A assignment: thread -> (row, 16-float segment of 64-k chunk)
    const int ar  = tid >> 2;                   // 0..127
    const int akg = tid & 3;                    // 0..3
    const uint32_t a_rel = (uint32_t)(ar * AROWB + akg * 32);

    // ldmatrix address components
    const uint32_t a_ldm_rel = (uint32_t)(A_OFF + (wg * 64 + (lane & 15)) * AROWB + (lane >> 4) * 16);
    const int nofs  = (lane & 7) + ((lane >> 4) & 1) * 8;
    const int khalf = (lane >> 3) & 1;
    const uint32_t b_ldm_rel0 = (uint32_t)(W_OFF + (wn * 32 + nofs) * WROWB + khalf * 16);

    const float* sv = (const float*)(smem + SV_OFF);
    float* red = (float*)(smem + RED_OFF);

    float c[4][4][4];
#pragma unroll
    for (int i = 0; i < 4; i++)
#pragma unroll
        for (int j = 0; j < 4; j++)
#pragma unroll
            for (int r = 0; r < 4; r++) c[i][j][r] = 0.f;

    int tile  = blockIdx.x;
    int chunk = 0;
    int par   = 0;

    float4 f[4];
    // ---- prologue: stage chunk (tile,0) into buf0; load f = chunk (tile,1)
    {
        const float* ap = X + ((size_t)tile * 128 + ar) * DD + akg * 16;
#pragma unroll
        for (int q = 0; q < 4; q++) f[q] = *(const float4*)(ap + q * 4);
        uint4 h0, h1;
        h0.x = pack_h2(f[0].x, f[0].y); h0.y = pack_h2(f[0].z, f[0].w);
        h0.z = pack_h2(f[1].x, f[1].y); h0.w = pack_h2(f[1].z, f[1].w);
        h1.x = pack_h2(f[2].x, f[2].y); h1.y = pack_h2(f[2].z, f[2].w);
        h1.z = pack_h2(f[3].x, f[3].y); h1.w = pack_h2(f[3].z, f[3].w);
        *(uint4*)(smem + A_OFF + a_rel)      = h0;
        *(uint4*)(smem + A_OFF + a_rel + 16) = h1;
        uint4* xs = (uint4*)(g_Xh + ((size_t)tile * 128 + ar) * DD + akg * 16);
        xs[0] = h0; xs[1] = h1;
        const float* ap1 = X + ((size_t)tile * 128 + ar) * DD + KC + akg * 16;
#pragma unroll
        for (int q = 0; q < 4; q++) f[q] = *(const float4*)(ap1 + q * 4);
    }
    CP_WAIT0();
    __syncthreads();   // publish W + v + chunk 0

    while (tile < NTILES) {
        // next-chunk indices
        int t1 = tile, c1 = chunk + 1;
        if (c1 == 4) { c1 = 0; t1 += NSM; }

        // 1. stage chunk (t1,c1) from f into the other buffer (overlaps compute)
        if (t1 < NTILES) {
            const uint32_t dst = A_OFF + (uint32_t)(par ^ 1) * ABUF + a_rel;
            uint4 h0, h1;
            h0.x = pack_h2(f[0].x, f[0].y); h0.y = pack_h2(f[0].z, f[0].w);
            h0.z = pack_h2(f[1].x, f[1].y); h0.w = pack_h2(f[1].z, f[1].w);
            h1.x = pack_h2(f[2].x, f[2].y); h1.y = pack_h2(f[2].z, f[2].w);
            h1.z = pack_h2(f[3].x, f[3].y); h1.w = pack_h2(f[3].z, f[3].w);
            *(uint4*)(smem + dst)      = h0;
            *(uint4*)(smem + dst + 16) = h1;
            uint4* xs = (uint4*)(g_Xh + ((size_t)t1 * 128 + ar) * DD + c1 * KC + akg * 16);
            xs[0] = h0; xs[1] = h1;
        }

        // 2. LDG chunk (t2,c2) into f
        int t2 = t1, c2 = c1 + 1;
        if (c2 == 4) { c2 = 0; t2 += NSM; }
        if (t2 < NTILES) {
            const float* ap = X + ((size_t)t2 * 128 + ar) * DD + c2 * KC + akg * 16;
#pragma unroll
            for (int q = 0; q < 4; q++) f[q] = *(const float4*)(ap + q * 4);
        }

        // 3. compute 4 k16-steps on chunk (tile,chunk) from buffer 'par'
        const uint32_t abuf = sb + A_OFF + (uint32_t)par * ABUF;
        const uint32_t wkb  = (uint32_t)(chunk * 128);
#pragma unroll
        for (int s = 0; s < 4; s++) {
            uint32_t bh[8];
#pragma unroll
            for (int jp = 0; jp < 2; jp++) {
                uint32_t ba = sb + b_ldm_rel0 + jp * 16 * WROWB + wkb + s * 32;
                ldm4(&bh[jp * 4], ba);
            }
#pragma unroll
            for (int i = 0; i < 4; i++) {
                uint32_t ah[4];
                uint32_t aa = abuf + (a_ldm_rel - A_OFF) + i * 16 * AROWB + s * 32;
                ldm4(ah, aa);
#pragma unroll
                for (int j = 0; j < 4; j++)
                    mma16816(c[i][j], ah, &bh[j * 2]);
            }
        }

        // 4. epilogue at tile end
        if (chunk == 3) {
            float mv0[4], mv1[4];
#pragma unroll
            for (int j = 0; j < 4; j++) {
                int col = wn * 32 + j * 8 + (lane & 3) * 2;
                mv0[j] = sv[col];
                mv1[j] = sv[col + 1];
            }
#pragma unroll
            for (int i = 0; i < 4; i++) {
#pragma unroll
                for (int rh = 0; rh < 2; rh++) {
                    float p = 0.f;
#pragma unroll
                    for (int j = 0; j < 4; j++) {
                        p = fmaf(fast_tanh(c[i][j][rh * 2 + 0]), mv0[j], p);
                        p = fmaf(fast_tanh(c[i][j][rh * 2 + 1]), mv1[j], p);
                    }
                    p += __shfl_xor_sync(0xffffffffu, p, 1);
                    p += __shfl_xor_sync(0xffffffffu, p, 2);
                    if ((lane & 3) == 0)
                        red[(wg * 64 + i * 16 + rh * 8 + (lane >> 2)) * 8 + wn] = p;
                }
            }
            __syncthreads();
            if (tid < 128) {
                float s = 0.f;
#pragma unroll
                for (int w = 0; w < 8; w++) s += red[tid * 8 + w];
                g_scores[(size_t)tile * 128 + tid] = s;
            }
#pragma unroll
            for (int i = 0; i < 4; i++)
#pragma unroll
                for (int j = 0; j < 4; j++)
#pragma unroll
                    for (int r = 0; r < 4; r++) c[i][j][r] = 0.f;
        }

        __syncthreads();   // staged chunk (t1,c1) visible; buffer 'par' reusable
        tile = t1; chunk = c1; par ^= 1;
    }
}

// ---------------- phase 2: softmax over T per batch -------------------------
__global__ void softmax_kernel(float* __restrict__ weights)
{
    const int b   = blockIdx.x;
    const int tid = threadIdx.x;
    const float* s = g_scores + (size_t)b * TT;
    __shared__ float red[256];

    float sc[16];
    float m = -INFINITY;
#pragma unroll
    for (int i = 0; i < 16; i++) {
        sc[i] = s[tid + i * 256];
        m = fmaxf(m, sc[i]);
    }
    red[tid] = m;
    __syncthreads();
    for (int st = 128; st > 0; st >>= 1) {
        if (tid < st) red[tid] = fmaxf(red[tid], red[tid + st]);
        __syncthreads();
    }
    m = red[0];
    __syncthreads();

    float sum = 0.f;
#pragma unroll
    for (int i = 0; i < 16; i++) {
        sc[i] = expf(sc[i] - m);
        sum += sc[i];
    }
    red[tid] = sum;
    __syncthreads();
    for (int st = 128; st > 0; st >>= 1) {
        if (tid < st) red[tid] += red[tid + st];
        __syncthreads();
    }
    const float inv = 1.f / red[0];
#pragma unroll
    for (int i = 0; i < 16; i++)
        weights[(size_t)b * TT + tid + i * 256] = sc[i] * inv;
}

// ---------------- phase 3: context from fp16 X shadow ----------------------
// 1024 blocks x 256 threads: warp = 32 lanes x 8 halves = one 512B X row.
__global__ void __launch_bounds__(256)
ctx_part_kernel(const float* __restrict__ w)
{
    const int b   = blockIdx.x;
    const int seg = blockIdx.y;                 // 0..15, 256 timesteps each
    const int q   = threadIdx.x & 31;           // 8-half slot over d
    const int tr  = threadIdx.x >> 5;           // 0..7 t-lane
    const __half* xb = g_Xh + ((size_t)b * TT + seg * 256) * DD + q * 8;
    const float* wb = w + (size_t)b * TT + seg * 256;

    float acc[8];
#pragma unroll
    for (int e = 0; e < 8; e++) acc[e] = 0.f;

    for (int it = 0; it < 32; it += 4) {
#pragma unroll
        for (int u2 = 0; u2 < 4; u2++) {
            int t = (it + u2) * 8 + tr;
            float wt = wb[t];
            uint4 hv = *(const uint4*)(xb + (size_t)t * DD);
            const __half2* hp = (const __half2*)&hv;
#pragma unroll
            for (int e2 = 0; e2 < 4; e2++) {
                float2 xf = __half22float2(hp[e2]);
                acc[e2 * 2 + 0] = fmaf(wt, xf.x, acc[e2 * 2 + 0]);
                acc[e2 * 2 + 1] = fmaf(wt, xf.y, acc[e2 * 2 + 1]);
            }
        }
    }

    __shared__ float red[8][32][8];
#pragma unroll
    for (int e = 0; e < 8; e++) red[tr][q][e] = acc[e];
    __syncthreads();
    if (tr == 0) {
        float s[8];
#pragma unroll
        for (int e = 0; e < 8; e++) s[e] = red[0][q][e];
#pragma unroll
        for (int r = 1; r < 8; r++)
#pragma unroll
            for (int e = 0; e < 8; e++) s[e] += red[r][q][e];
        float* dst = &g_cpart[((size_t)seg * BB + b) * DD + q * 8];
#pragma unroll
        for (int e = 0; e < 8; e++) dst[e] = s[e];
    }
}

__global__ void ctx_final_kernel(float* __restrict__ ctx)
{
    const int b = blockIdx.x, d = threadIdx.x;
    float s = 0.f;
#pragma unroll
    for (int seg = 0; seg < 16; seg++)
        s += g_cpart[((size_t)seg * BB + b) * DD + d];
    ctx[(size_t)b * DD + d] = s;
}

// ---------------------------------------------------------------------------
extern "C" void kernel_launch(void* const* d_in, const int* in_sizes, int n_in,
                              void* d_out, int out_size)
{
    const float* X  = (const float*)d_in[0];
    const float* W1 = (const float*)d_in[1];
    const float* W2 = (const float*)d_in[2];
    const float* v  = (const float*)d_in[3];

    float* out     = (float*)d_out;
    float* ctx     = out;               // context_vector: B*D floats
    float* weights = out + BB * DD;     // attention_weights: B*T floats

    cudaFuncSetAttribute(score_mma_kernel,
                         cudaFuncAttributeMaxDynamicSharedMemorySize, SM_TOTAL);

    prep_w<<<256, 256>>>(W1, W2);
    score_mma_kernel<<<NSM, 512, SM_TOTAL>>>(X, v);
    softmax_kernel<<<BB, 256>>>(weights);
    ctx_part_kernel<<<dim3(BB, 16), 256>>>(weights);
    ctx_final_kernel<<<BB, 256>>>(ctx);
}

// round 12
// speedup vs baseline: 1.0935x; 1.0935x over previous
#include <cuda_runtime.h>
#include <cuda_fp16.h>
#include <math.h>
#include <stdint.h>

#define BB 64
#define TT 4096
#define DD 256
#define UU 256
#define NTILES 2048          // (BB*TT)/128
#define NSM 152

// ---------------- device-global scratch (allocation-free rule) -------------
__device__ float g_scores[BB * TT];
__device__ float g_cpart[16 * BB * DD];
__device__ __align__(16) __half g_WT[UU * DD];   // (W1+W2)^T fp16, [n][k]

// ---------------- smem layout for score kernel -----------------------------
#define KC      64           // k per A chunk
#define WROWB   528          // W row: 512B data + 16B pad
#define AROWB   144          // A row: 128B data + 16B pad
#define W_OFF   0            // 256 rows * 528B = 135168
#define A_OFF   135168       // 2 stages * 128 rows * 144B = 36864
#define ABUF    18432
#define RED_OFF 172032       // 128 rows * 8 warps * 4B = 4096
#define SV_OFF  176128       // 256 floats
#define SM_TOTAL 177152

// ---------------- PTX helpers (plain sm_103-legal: no 'a' features) --------
__device__ __forceinline__ uint32_t smem_u32(const void* p) {
    uint32_t a;
    asm("{ .reg .u64 t; cvta.to.shared.u64 t, %1; cvt.u32.u64 %0, t; }"
        : "=r"(a) : "l"(p));
    return a;
}
__device__ __forceinline__ void ldm4(uint32_t* r, uint32_t addr) {
    asm volatile("ldmatrix.sync.aligned.m8n8.x4.shared.b16 {%0,%1,%2,%3}, [%4];"
                 : "=r"(r[0]), "=r"(r[1]), "=r"(r[2]), "=r"(r[3]) : "r"(addr));
}
__device__ __forceinline__ void mma16816(float* c, const uint32_t* a, const uint32_t* b) {
    asm volatile(
        "mma.sync.aligned.m16n8k16.row.col.f32.f16.f16.f32 "
        "{%0,%1,%2,%3},{%4,%5,%6,%7},{%8,%9},{%0,%1,%2,%3};"
        : "+f"(c[0]), "+f"(c[1]), "+f"(c[2]), "+f"(c[3])
        : "r"(a[0]), "r"(a[1]), "r"(a[2]), "r"(a[3]), "r"(b[0]), "r"(b[1]));
}
__device__ __forceinline__ void cpa16(uint32_t dst, const void* src) {
    asm volatile("cp.async.ca.shared.global [%0], [%1], 16;" :: "r"(dst), "l"(src));
}
#define CP_COMMIT() asm volatile("cp.async.commit_group;" ::: "memory")
#define CP_WAIT0()  asm volatile("cp.async.wait_group 0;" ::: "memory")

__device__ __forceinline__ uint32_t pack_h2(float a, float b) {
    __half2 t = __floats2half2_rn(a, b);
    return *(uint32_t*)&t;
}
__device__ __forceinline__ float fast_tanh(float q) {
    float e = __expf(2.f * q);
    return 1.f - __fdividef(2.f, e + 1.f);   // exact limits at +/-inf
}

// ---------------- phase 0: fuse + transpose weights (fp16) -----------------
__global__ void prep_w(const float* __restrict__ W1, const float* __restrict__ W2)
{
    int idx = blockIdx.x * 256 + threadIdx.x;   // idx = k*256 + u
    int k = idx >> 8, u = idx & 255;
    g_WT[u * DD + k] = __float2half_rn(W1[idx] + W2[idx]);
}

// ---------------- phase 1: persistent HMMA GEMM + tanh/v epilogue ----------
// 152 persistent CTAs x 512 threads. W (256x256 fp16) resident in smem.
// Pipelined A staging. Processes tiles [tile0, tile_end) with stride NSM.
__global__ void __launch_bounds__(512, 1)
score_mma_kernel(const float* __restrict__ X, const float* __restrict__ v,
                 int tile0, int tile_end)
{
    extern __shared__ char smem[];
    const uint32_t sb = smem_u32(smem);
    const int tid  = threadIdx.x;
    const int wid  = tid >> 5, lane = tid & 31;
    const int wg   = wid >> 3, wn = wid & 7;

    // ---- prologue: W resident load (once) + v
    {
#pragma unroll
        for (int i = 0; i < 16; i++) {
            int u = tid + i * 512;              // 8192 16B-units
            int row = u >> 5, c16 = u & 31;
            cpa16(sb + W_OFF + row * WROWB + c16 * 16,
                  (const char*)(g_WT + (size_t)row * DD) + c16 * 16);
        }
        CP_COMMIT();
    }
    if (tid < 256) ((float*)(smem + SV_OFF))[tid] = v[tid];

    // A assignment: thread -> (row, 16-float segment of 64-k chunk)
    const int ar  = tid >> 2;                   // 0..127
    const int akg = tid & 3;                    // 0..3
    const uint32_t a_rel = (uint32_t)(ar * AROWB + akg * 32);

    // ldmatrix address components
    const uint32_t a_ldm_rel = (uint32_t)(A_OFF + (wg * 64 + (lane & 15)) * AROWB + (lane >> 4) * 16);
    const int nofs  = (lane & 7) + ((lane >> 4) & 1) * 8;
    const int khalf = (lane >> 3) & 1;
    const uint32_t b_ldm_rel0 = (uint32_t)(W_OFF + (wn * 32 + nofs) * WROWB + khalf * 16);

    const float* sv = (const float*)(smem + SV_OFF);
    float* red = (float*)(smem + RED_OFF);

    float c[4][4][4];
#pragma unroll
    for (int i = 0; i < 4; i++)
#pragma unroll
        for (int j = 0; j < 4; j++)
#pragma unroll
            for (int r = 0; r < 4; r++) c[i][j][r] = 0.f;

    int tile  = tile0 + blockIdx.x;
    int chunk = 0;
    int par   = 0;

    float4 f[4];
    if (tile < tile_end) {
        const float* ap = X + ((size_t)tile * 128 + ar) * DD + akg * 16;
#pragma unroll
        for (int q = 0; q < 4; q++) f[q] = *(const float4*)(ap + q * 4);
        uint4 h0, h1;
        h0.x = pack_h2(f[0].x, f[0].y); h0.y = pack_h2(f[0].z, f[0].w);
        h0.z = pack_h2(f[1].x, f[1].y); h0.w = pack_h2(f[1].z, f[1].w);
        h1.x = pack_h2(f[2].x, f[2].y); h1.y = pack_h2(f[2].z, f[2].w);
        h1.z = pack_h2(f[3].x, f[3].y); h1.w = pack_h2(f[3].z, f[3].w);
        *(uint4*)(smem + A_OFF + a_rel)      = h0;
        *(uint4*)(smem + A_OFF + a_rel + 16) = h1;
        const float* ap1 = X + ((size_t)tile * 128 + ar) * DD + KC + akg * 16;
#pragma unroll
        for (int q = 0; q < 4; q++) f[q] = *(const float4*)(ap1 + q * 4);
    }
    CP_WAIT0();
    __syncthreads();   // publish W + v + chunk 0

    while (tile < tile_end) {
        // next-chunk indices
        int t1 = tile, c1 = chunk + 1;
        if (c1 == 4) { c1 = 0; t1 += NSM; }

        // 1. stage chunk (t1,c1) from f into the other buffer (overlaps compute)
        if (t1 < tile_end) {
            const uint32_t dst = A_OFF + (uint32_t)(par ^ 1) * ABUF + a_rel;
            uint4 h0, h1;
            h0.x = pack_h2(f[0].x, f[0].y); h0.y = pack_h2(f[0].z, f[0].w);
            h0.z = pack_h2(f[1].x, f[1].y); h0.w = pack_h2(f[1].z, f[1].w);
            h1.x = pack_h2(f[2].x, f[2].y); h1.y = pack_h2(f[2].z, f[2].w);
            h1.z = pack_h2(f[3].x, f[3].y); h1.w = pack_h2(f[3].z, f[3].w);
            *(uint4*)(smem + dst)      = h0;
            *(uint4*)(smem + dst + 16) = h1;
        }

        // 2. LDG chunk (t2,c2) into f
        int t2 = t1, c2 = c1 + 1;
        if (c2 == 4) { c2 = 0; t2 += NSM; }
        if (t2 < tile_end) {
            const float* ap = X + ((size_t)t2 * 128 + ar) * DD + c2 * KC + akg * 16;
#pragma unroll
            for (int q = 0; q < 4; q++) f[q] = *(const float4*)(ap + q * 4);
        }

        // 3. compute 4 k16-steps on chunk (tile,chunk) from buffer 'par'
        const uint32_t abuf = sb + A_OFF + (uint32_t)par * ABUF;
        const uint32_t wkb  = (uint32_t)(chunk * 128);
#pragma unroll
        for (int s = 0; s < 4; s++) {
            uint32_t bh[8];
#pragma unroll
            for (int jp = 0; jp < 2; jp++) {
                uint32_t ba = sb + b_ldm_rel0 + jp * 16 * WROWB + wkb + s * 32;
                ldm4(&bh[jp * 4], ba);
            }
#pragma unroll
            for (int i = 0; i < 4; i++) {
                uint32_t ah[4];
                uint32_t aa = abuf + (a_ldm_rel - A_OFF) + i * 16 * AROWB + s * 32;
                ldm4(ah, aa);
#pragma unroll
                for (int j = 0; j < 4; j++)
                    mma16816(c[i][j], ah, &bh[j * 2]);
            }
        }

        // 4. epilogue at tile end
        if (chunk == 3) {
            float mv0[4], mv1[4];
#pragma unroll
            for (int j = 0; j < 4; j++) {
                int col = wn * 32 + j * 8 + (lane & 3) * 2;
                mv0[j] = sv[col];
                mv1[j] = sv[col + 1];
            }
#pragma unroll
            for (int i = 0; i < 4; i++) {
#pragma unroll
                for (int rh = 0; rh < 2; rh++) {
                    float p = 0.f;
#pragma unroll
                    for (int j = 0; j < 4; j++) {
                        p = fmaf(fast_tanh(c[i][j][rh * 2 + 0]), mv0[j], p);
                        p = fmaf(fast_tanh(c[i][j][rh * 2 + 1]), mv1[j], p);
                    }
                    p += __shfl_xor_sync(0xffffffffu, p, 1);
                    p += __shfl_xor_sync(0xffffffffu, p, 2);
                    if ((lane & 3) == 0)
                        red[(wg * 64 + i * 16 + rh * 8 + (lane >> 2)) * 8 + wn] = p;
                }
            }
            __syncthreads();
            if (tid < 128) {
                float s = 0.f;
#pragma unroll
                for (int w = 0; w < 8; w++) s += red[tid * 8 + w];
                g_scores[(size_t)tile * 128 + tid] = s;
            }
#pragma unroll
            for (int i = 0; i < 4; i++)
#pragma unroll
                for (int j = 0; j < 4; j++)
#pragma unroll
                    for (int r = 0; r < 4; r++) c[i][j][r] = 0.f;
        }

        __syncthreads();   // staged chunk (t1,c1) visible; buffer 'par' reusable
        tile = t1; chunk = c1; par ^= 1;
    }
}

// ---------------- phase 2: softmax over T per batch -------------------------
__global__ void softmax_kernel(float* __restrict__ weights, int b0)
{
    const int b   = blockIdx.x + b0;
    const int tid = threadIdx.x;
    const float* s = g_scores + (size_t)b * TT;
    __shared__ float red[256];

    float sc[16];
    float m = -INFINITY;
#pragma unroll
    for (int i = 0; i < 16; i++) {
        sc[i] = s[tid + i * 256];
        m = fmaxf(m, sc[i]);
    }
    red[tid] = m;
    __syncthreads();
    for (int st = 128; st > 0; st >>= 1) {
        if (tid < st) red[tid] = fmaxf(red[tid], red[tid + st]);
        __syncthreads();
    }
    m = red[0];
    __syncthreads();

    float sum = 0.f;
#pragma unroll
    for (int i = 0; i < 16; i++) {
        sc[i] = expf(sc[i] - m);
        sum += sc[i];
    }
    red[tid] = sum;
    __syncthreads();
    for (int st = 128; st > 0; st >>= 1) {
        if (tid < st) red[tid] += red[tid + st];
        __syncthreads();
    }
    const float inv = 1.f / red[0];
#pragma unroll
    for (int i = 0; i < 16; i++)
        weights[(size_t)b * TT + tid + i * 256] = sc[i] * inv;
}

// ---------------- phase 3: context, 2-stage (float4, fp32 X) ---------------
__global__ void __launch_bounds__(256)
ctx_part_kernel(const float* __restrict__ X, const float* __restrict__ w, int b0)
{
    const int b   = blockIdx.x + b0;
    const int seg = blockIdx.y;                 // 0..15, 256 timesteps each
    const int q   = threadIdx.x & 63;           // float4 slot over d
    const int tr  = threadIdx.x >> 6;           // 0..3 t-lane
    const float* xb = X + ((size_t)b * TT + seg * 256) * DD + q * 4;
    const float* wb = w + (size_t)b * TT + seg * 256;

    float4 acc = make_float4(0.f, 0.f, 0.f, 0.f);
    for (int it = 0; it < 64; it += 4) {
#pragma unroll
        for (int u2 = 0; u2 < 4; u2++) {
            int t = (it + u2) * 4 + tr;
            float wt = wb[t];
            float4 xv = *(const float4*)(xb + (size_t)t * DD);
            acc.x = fmaf(wt, xv.x, acc.x);
            acc.y = fmaf(wt, xv.y, acc.y);
            acc.z = fmaf(wt, xv.z, acc.z);
            acc.w = fmaf(wt, xv.w, acc.w);
        }
    }

    __shared__ float4 red[256];
    red[threadIdx.x] = acc;
    __syncthreads();
    if (tr == 0) {
        float4 a = red[q], b4 = red[q + 64], c4 = red[q + 128], d4 = red[q + 192];
        float4 r;
        r.x = (a.x + b4.x) + (c4.x + d4.x);
        r.y = (a.y + b4.y) + (c4.y + d4.y);
        r.z = (a.z + b4.z) + (c4.z + d4.z);
        r.w = (a.w + b4.w) + (c4.w + d4.w);
        *(float4*)&g_cpart[((size_t)seg * BB + b) * DD + q * 4] = r;
    }
}

__global__ void ctx_final_kernel(float* __restrict__ ctx)
{
    const int b = blockIdx.x, d = threadIdx.x;
    float s = 0.f;
#pragma unroll
    for (int seg = 0; seg < 16; seg++)
        s += g_cpart[((size_t)seg * BB + b) * DD + d];
    ctx[(size_t)b * DD + d] = s;
}

// ---------------------------------------------------------------------------
extern "C" void kernel_launch(void* const* d_in, const int* in_sizes, int n_in,
                              void* d_out, int out_size)
{
    const float* X  = (const float*)d_in[0];
    const float* W1 = (const float*)d_in[1];
    const float* W2 = (const float*)d_in[2];
    const float* v  = (const float*)d_in[3];

    float* out     = (float*)d_out;
    float* ctx     = out;               // context_vector: B*D floats
    float* weights = out + BB * DD;     // attention_weights: B*T floats

    static cudaStream_t s2;
    static cudaEvent_t evA, evB;
    static int inited = 0;
    if (!inited) {
        cudaStreamCreateWithFlags(&s2, cudaStreamNonBlocking);
        cudaEventCreateWithFlags(&evA, cudaEventDisableTiming);
        cudaEventCreateWithFlags(&evB, cudaEventDisableTiming);
        cudaFuncSetAttribute(score_mma_kernel,
                             cudaFuncAttributeMaxDynamicSharedMemorySize, SM_TOTAL);
        inited = 1;
    }

    const int HALF = NTILES / 2;        // 1024 tiles = batches 0-31

    prep_w<<<256, 256>>>(W1, W2);
    // score half 0 (batches 0-31)
    score_mma_kernel<<<NSM, 512, SM_TOTAL>>>(X, v, 0, HALF);
    cudaEventRecord(evA, 0);

    // stream 2: softmax + ctx for batches 0-31, overlapping score half 1
    cudaStreamWaitEvent(s2, evA, 0);
    softmax_kernel<<<32, 256, 0, s2>>>(weights, 0);
    ctx_part_kernel<<<dim3(32, 16), 256, 0, s2>>>(X, weights, 0);
    cudaEventRecord(evB, s2);

    // main stream: score half 1 (batches 32-63), then its softmax + ctx
    score_mma_kernel<<<NSM, 512, SM_TOTAL>>>(X, v, HALF, NTILES);
    softmax_kernel<<<32, 256>>>(weights, 32);
    ctx_part_kernel<<<dim3(32, 16), 256>>>(X, weights, 32);

    // join and finalize
    cudaStreamWaitEvent(0, evB, 0);
    ctx_final_kernel<<<BB, 256>>>(ctx);
}

// round 13
// speedup vs baseline: 1.1195x; 1.0238x over previous
#include <cuda_runtime.h>
#include <cuda_fp16.h>
#include <math.h>
#include <stdint.h>

#define BB 64
#define TT 4096
#define DD 256
#define UU 256
#define NTILES 2048          // (BB*TT)/128
#define NSM 152

// ---------------- device-global scratch (allocation-free rule) -------------
__device__ float g_scores[BB * TT];
__device__ float g_cpart[16 * BB * DD];
__device__ __align__(16) __half g_WT[UU * DD];   // (W1+W2)^T fp16, [n][k]

// ---------------- smem layout for score kernel -----------------------------
#define KC      64           // k per A chunk
#define WROWB   528          // W row: 512B data + 16B pad
#define AROWB   144          // A row: 128B data + 16B pad
#define W_OFF   0            // 256 rows * 528B = 135168
#define A_OFF   135168       // 2 stages * 128 rows * 144B = 36864
#define ABUF    18432
#define RED_OFF 172032       // 128 rows * 8 warps * 4B = 4096
#define SV_OFF  176128       // 256 floats
#define SM_TOTAL 177152

// ---------------- PTX helpers (plain sm_103-legal: no 'a' features) --------
__device__ __forceinline__ uint32_t smem_u32(const void* p) {
    uint32_t a;
    asm("{ .reg .u64 t; cvta.to.shared.u64 t, %1; cvt.u32.u64 %0, t; }"
        : "=r"(a) : "l"(p));
    return a;
}
__device__ __forceinline__ void ldm4(uint32_t* r, uint32_t addr) {
    asm volatile("ldmatrix.sync.aligned.m8n8.x4.shared.b16 {%0,%1,%2,%3}, [%4];"
                 : "=r"(r[0]), "=r"(r[1]), "=r"(r[2]), "=r"(r[3]) : "r"(addr));
}
__device__ __forceinline__ void mma16816(float* c, const uint32_t* a, const uint32_t* b) {
    asm volatile(
        "mma.sync.aligned.m16n8k16.row.col.f32.f16.f16.f32 "
        "{%0,%1,%2,%3},{%4,%5,%6,%7},{%8,%9},{%0,%1,%2,%3};"
        : "+f"(c[0]), "+f"(c[1]), "+f"(c[2]), "+f"(c[3])
        : "r"(a[0]), "r"(a[1]), "r"(a[2]), "r"(a[3]), "r"(b[0]), "r"(b[1]));
}
__device__ __forceinline__ void cpa16(uint32_t dst, const void* src) {
    asm volatile("cp.async.ca.shared.global [%0], [%1], 16;" :: "r"(dst), "l"(src));
}
#define CP_COMMIT() asm volatile("cp.async.commit_group;" ::: "memory")
#define CP_WAIT0()  asm volatile("cp.async.wait_group 0;" ::: "memory")

__device__ __forceinline__ uint32_t pack_h2(float a, float b) {
    __half2 t = __floats2half2_rn(a, b);
    return *(uint32_t*)&t;
}
__device__ __forceinline__ float fast_tanh(float q) {
    float e = __expf(2.f * q);
    return 1.f - __fdividef(2.f, e + 1.f);   // exact limits at +/-inf
}

// ---------------- phase 0: fuse + transpose weights (fp16) -----------------
__global__ void prep_w(const float* __restrict__ W1, const float* __restrict__ W2)
{
    int idx = blockIdx.x * 256 + threadIdx.x;   // idx = k*256 + u
    int k = idx >> 8, u = idx & 255;
    g_WT[u * DD + k] = __float2half_rn(W1[idx] + W2[idx]);
}

// ---------------- phase 1: persistent HMMA GEMM + tanh/v epilogue ----------
// 152 persistent CTAs x 512 threads, capped at 112 regs/thread so the
// 128-thread softmax/ctx kernels can co-schedule during the overlap phase.
__global__ void __maxnreg__(112)
score_mma_kernel(const float* __restrict__ X, const float* __restrict__ v,
                 int tile0, int tile_end)
{
    extern __shared__ char smem[];
    const uint32_t sb = smem_u32(smem);
    const int tid  = threadIdx.x;
    const int wid  = tid >> 5, lane = tid & 31;
    const int wg   = wid >> 3, wn = wid & 7;

    // ---- prologue: W resident load (once) + v
    {
#pragma unroll
        for (int i = 0; i < 16; i++) {
            int u = tid + i * 512;              // 8192 16B-units
            int row = u >> 5, c16 = u & 31;
            cpa16(sb + W_OFF + row * WROWB + c16 * 16,
                  (const char*)(g_WT + (size_t)row * DD) + c16 * 16);
        }
        CP_COMMIT();
    }
    if (tid < 256) ((float*)(smem + SV_OFF))[tid] = v[tid];

    // A assignment: thread -> (row, 16-float segment of 64-k chunk)
    const int ar  = tid >> 2;                   // 0..127
    const int akg = tid & 3;                    // 0..3
    const uint32_t a_rel = (uint32_t)(ar * AROWB + akg * 32);

    // ldmatrix address components
    const uint32_t a_ldm_rel = (uint32_t)(A_OFF + (wg * 64 + (lane & 15)) * AROWB + (lane >> 4) * 16);
    const int nofs  = (lane & 7) + ((lane >> 4) & 1) * 8;
    const int khalf = (lane >> 3) & 1;
    const uint32_t b_ldm_rel0 = (uint32_t)(W_OFF + (wn * 32 + nofs) * WROWB + khalf * 16);

    const float* sv = (const float*)(smem + SV_OFF);
    float* red = (float*)(smem + RED_OFF);

    float c[4][4][4];
#pragma unroll
    for (int i = 0; i < 4; i++)
#pragma unroll
        for (int j = 0; j < 4; j++)
#pragma unroll
            for (int r = 0; r < 4; r++) c[i][j][r] = 0.f;

    int tile  = tile0 + blockIdx.x;
    int chunk = 0;
    int par   = 0;

    float4 f[4];
    if (tile < tile_end) {
        const float* ap = X + ((size_t)tile * 128 + ar) * DD + akg * 16;
#pragma unroll
        for (int q = 0; q < 4; q++) f[q] = *(const float4*)(ap + q * 4);
        uint4 h0, h1;
        h0.x = pack_h2(f[0].x, f[0].y); h0.y = pack_h2(f[0].z, f[0].w);
        h0.z = pack_h2(f[1].x, f[1].y); h0.w = pack_h2(f[1].z, f[1].w);
        h1.x = pack_h2(f[2].x, f[2].y); h1.y = pack_h2(f[2].z, f[2].w);
        h1.z = pack_h2(f[3].x, f[3].y); h1.w = pack_h2(f[3].z, f[3].w);
        *(uint4*)(smem + A_OFF + a_rel)      = h0;
        *(uint4*)(smem + A_OFF + a_rel + 16) = h1;
        const float* ap1 = X + ((size_t)tile * 128 + ar) * DD + KC + akg * 16;
#pragma unroll
        for (int q = 0; q < 4; q++) f[q] = *(const float4*)(ap1 + q * 4);
    }
    CP_WAIT0();
    __syncthreads();   // publish W + v + chunk 0

    while (tile < tile_end) {
        // next-chunk indices
        int t1 = tile, c1 = chunk + 1;
        if (c1 == 4) { c1 = 0; t1 += NSM; }

        // 1. stage chunk (t1,c1) from f into the other buffer (overlaps compute)
        if (t1 < tile_end) {
            const uint32_t dst = A_OFF + (uint32_t)(par ^ 1) * ABUF + a_rel;
            uint4 h0, h1;
            h0.x = pack_h2(f[0].x, f[0].y); h0.y = pack_h2(f[0].z, f[0].w);
            h0.z = pack_h2(f[1].x, f[1].y); h0.w = pack_h2(f[1].z, f[1].w);
            h1.x = pack_h2(f[2].x, f[2].y); h1.y = pack_h2(f[2].z, f[2].w);
            h1.z = pack_h2(f[3].x, f[3].y); h1.w = pack_h2(f[3].z, f[3].w);
            *(uint4*)(smem + dst)      = h0;
            *(uint4*)(smem + dst + 16) = h1;
        }

        // 2. LDG chunk (t2,c2) into f
        int t2 = t1, c2 = c1 + 1;
        if (c2 == 4) { c2 = 0; t2 += NSM; }
        if (t2 < tile_end) {
            const float* ap = X + ((size_t)t2 * 128 + ar) * DD + c2 * KC + akg * 16;
#pragma unroll
            for (int q = 0; q < 4; q++) f[q] = *(const float4*)(ap + q * 4);
        }

        // 3. compute 4 k16-steps on chunk (tile,chunk) from buffer 'par'
        const uint32_t abuf = sb + A_OFF + (uint32_t)par * ABUF;
        const uint32_t wkb  = (uint32_t)(chunk * 128);
#pragma unroll
        for (int s = 0; s < 4; s++) {
            uint32_t bh[8];
#pragma unroll
            for (int jp = 0; jp < 2; jp++) {
                uint32_t ba = sb + b_ldm_rel0 + jp * 16 * WROWB + wkb + s * 32;
                ldm4(&bh[jp * 4], ba);
            }
#pragma unroll
            for (int i = 0; i < 4; i++) {
                uint32_t ah[4];
                uint32_t aa = abuf + (a_ldm_rel - A_OFF) + i * 16 * AROWB + s * 32;
                ldm4(ah, aa);
#pragma unroll
                for (int j = 0; j < 4; j++)
                    mma16816(c[i][j], ah, &bh[j * 2]);
            }
        }

        // 4. epilogue at tile end
        if (chunk == 3) {
            float mv0[4], mv1[4];
#pragma unroll
            for (int j = 0; j < 4; j++) {
                int col = wn * 32 + j * 8 + (lane & 3) * 2;
                mv0[j] = sv[col];
                mv1[j] = sv[col + 1];
            }
#pragma unroll
            for (int i = 0; i < 4; i++) {
#pragma unroll
                for (int rh = 0; rh < 2; rh++) {
                    float p = 0.f;
#pragma unroll
                    for (int j = 0; j < 4; j++) {
                        p = fmaf(fast_tanh(c[i][j][rh * 2 + 0]), mv0[j], p);
                        p = fmaf(fast_tanh(c[i][j][rh * 2 + 1]), mv1[j], p);
                    }
                    p += __shfl_xor_sync(0xffffffffu, p, 1);
                    p += __shfl_xor_sync(0xffffffffu, p, 2);
                    if ((lane & 3) == 0)
                        red[(wg * 64 + i * 16 + rh * 8 + (lane >> 2)) * 8 + wn] = p;
                }
            }
            __syncthreads();
            if (tid < 128) {
                float s = 0.f;
#pragma unroll
                for (int w = 0; w < 8; w++) s += red[tid * 8 + w];
                g_scores[(size_t)tile * 128 + tid] = s;
            }
#pragma unroll
            for (int i = 0; i < 4; i++)
#pragma unroll
                for (int j = 0; j < 4; j++)
#pragma unroll
                    for (int r = 0; r < 4; r++) c[i][j][r] = 0.f;
        }

        __syncthreads();   // staged chunk (t1,c1) visible; buffer 'par' reusable
        tile = t1; chunk = c1; par ^= 1;
    }
}

// ---------------- phase 2: softmax over T per batch (128 thr, co-residable)-
__global__ void __launch_bounds__(128)
softmax_kernel(float* __restrict__ weights, int b0)
{
    const int b   = blockIdx.x + b0;
    const int tid = threadIdx.x;
    const float* s = g_scores + (size_t)b * TT;
    __shared__ float red[128];

    float sc[32];
    float m = -INFINITY;
#pragma unroll
    for (int i = 0; i < 32; i++) {
        sc[i] = s[tid + i * 128];
        m = fmaxf(m, sc[i]);
    }
    red[tid] = m;
    __syncthreads();
    for (int st = 64; st > 0; st >>= 1) {
        if (tid < st) red[tid] = fmaxf(red[tid], red[tid + st]);
        __syncthreads();
    }
    m = red[0];
    __syncthreads();

    float sum = 0.f;
#pragma unroll
    for (int i = 0; i < 32; i++) {
        sc[i] = expf(sc[i] - m);
        sum += sc[i];
    }
    red[tid] = sum;
    __syncthreads();
    for (int st = 64; st > 0; st >>= 1) {
        if (tid < st) red[tid] += red[tid + st];
        __syncthreads();
    }
    const float inv = 1.f / red[0];
#pragma unroll
    for (int i = 0; i < 32; i++)
        weights[(size_t)b * TT + tid + i * 128] = sc[i] * inv;
}

// ---------------- phase 3: context (128 thr blocks, co-residable) ----------
__global__ void __launch_bounds__(128)
ctx_part_kernel(const float* __restrict__ X, const float* __restrict__ w, int b0)
{
    const int b   = blockIdx.x + b0;
    const int seg = blockIdx.y;                 // 0..15, 256 timesteps each
    const int q   = threadIdx.x & 63;           // float4 slot over d
    const int tr  = threadIdx.x >> 6;           // 0..1 t-lane
    const float* xb = X + ((size_t)b * TT + seg * 256) * DD + q * 4;
    const float* wb = w + (size_t)b * TT + seg * 256;

    float4 acc = make_float4(0.f, 0.f, 0.f, 0.f);
    for (int it = 0; it < 128; it += 4) {
#pragma unroll
        for (int u2 = 0; u2 < 4; u2++) {
            int t = (it + u2) * 2 + tr;
            float wt = wb[t];
            float4 xv = *(const float4*)(xb + (size_t)t * DD);
            acc.x = fmaf(wt, xv.x, acc.x);
            acc.y = fmaf(wt, xv.y, acc.y);
            acc.z = fmaf(wt, xv.z, acc.z);
            acc.w = fmaf(wt, xv.w, acc.w);
        }
    }

    __shared__ float4 red[128];
    red[threadIdx.x] = acc;
    __syncthreads();
    if (tr == 0) {
        float4 a = red[q], b4 = red[q + 64];
        float4 r;
        r.x = a.x + b4.x; r.y = a.y + b4.y;
        r.z = a.z + b4.z; r.w = a.w + b4.w;
        *(float4*)&g_cpart[((size_t)seg * BB + b) * DD + q * 4] = r;
    }
}

__global__ void ctx_final_kernel(float* __restrict__ ctx)
{
    const int b = blockIdx.x, d = threadIdx.x;
    float s = 0.f;
#pragma unroll
    for (int seg = 0; seg < 16; seg++)
        s += g_cpart[((size_t)seg * BB + b) * DD + d];
    ctx[(size_t)b * DD + d] = s;
}

// ---------------------------------------------------------------------------
extern "C" void kernel_launch(void* const* d_in, const int* in_sizes, int n_in,
                              void* d_out, int out_size)
{
    const float* X  = (const float*)d_in[0];
    const float* W1 = (const float*)d_in[1];
    const float* W2 = (const float*)d_in[2];
    const float* v  = (const float*)d_in[3];

    float* out     = (float*)d_out;
    float* ctx     = out;               // context_vector: B*D floats
    float* weights = out + BB * DD;     // attention_weights: B*T floats

    static cudaStream_t s2;
    static cudaEvent_t evA, evB;
    static int inited = 0;
    if (!inited) {
        cudaStreamCreateWithFlags(&s2, cudaStreamNonBlocking);
        cudaEventCreateWithFlags(&evA, cudaEventDisableTiming);
        cudaEventCreateWithFlags(&evB, cudaEventDisableTiming);
        cudaFuncSetAttribute(score_mma_kernel,
                             cudaFuncAttributeMaxDynamicSharedMemorySize, SM_TOTAL);
        inited = 1;
    }

    const int HALF = NTILES / 2;        // 1024 tiles = batches 0-31

    prep_w<<<256, 256>>>(W1, W2);
    // score half 0 (batches 0-31)
    score_mma_kernel<<<NSM, 512, SM_TOTAL>>>(X, v, 0, HALF);
    cudaEventRecord(evA, 0);

    // stream 2: softmax + ctx for batches 0-31, overlapping score half 1
    cudaStreamWaitEvent(s2, evA, 0);
    softmax_kernel<<<32, 128, 0, s2>>>(weights, 0);
    ctx_part_kernel<<<dim3(32, 16), 128, 0, s2>>>(X, weights, 0);
    cudaEventRecord(evB, s2);

    // main stream: score half 1 (batches 32-63), then its softmax + ctx
    score_mma_kernel<<<NSM, 512, SM_TOTAL>>>(X, v, HALF, NTILES);
    softmax_kernel<<<32, 128>>>(weights, 32);
    ctx_part_kernel<<<dim3(32, 16), 128>>>(X, weights, 32);

    // join and finalize
    cudaStreamWaitEvent(0, evB, 0);
    ctx_final_kernel<<<BB, 256>>>(ctx);
}

// round 14
// speedup vs baseline: 1.2462x; 1.1132x over previous
#include <cuda_runtime.h>
#include <cuda_fp16.h>
#include <math.h>
#include <stdint.h>

#define BB 64
#define TT 4096
#define DD 256
#define UU 256
#define NTILES 2048          // (BB*TT)/128
#define NSM 152

// ---------------- device-global scratch (allocation-free rule) -------------
__device__ float g_scores[BB * TT];
__device__ float g_cpart[16 * BB * DD];
__device__ __align__(16) __half g_WT[UU * DD];   // (W1+W2)^T fp16, [n][k]

// ---------------- smem layout for score kernel -----------------------------
#define KC      64           // k per A chunk
#define WROWB   528          // W row: 512B data + 16B pad
#define AROWB   144          // A row: 128B data + 16B pad
#define W_OFF   0            // 256 rows * 528B = 135168
#define A_OFF   135168       // 2 stages * 128 rows * 144B = 36864
#define ABUF    18432
#define RED_OFF 172032       // 128 rows * 8 warps * 4B = 4096
#define SV_OFF  176128       // 256 floats
#define SM_TOTAL 177152

// ---------------- PTX helpers (plain sm_103-legal: no 'a' features) --------
__device__ __forceinline__ uint32_t smem_u32(const void* p) {
    uint32_t a;
    asm("{ .reg .u64 t; cvta.to.shared.u64 t, %1; cvt.u32.u64 %0, t; }"
        : "=r"(a) : "l"(p));
    return a;
}
__device__ __forceinline__ void ldm4(uint32_t* r, uint32_t addr) {
    asm volatile("ldmatrix.sync.aligned.m8n8.x4.shared.b16 {%0,%1,%2,%3}, [%4];"
                 : "=r"(r[0]), "=r"(r[1]), "=r"(r[2]), "=r"(r[3]) : "r"(addr));
}
__device__ __forceinline__ void mma16816(float* c, const uint32_t* a, const uint32_t* b) {
    asm volatile(
        "mma.sync.aligned.m16n8k16.row.col.f32.f16.f16.f32 "
        "{%0,%1,%2,%3},{%4,%5,%6,%7},{%8,%9},{%0,%1,%2,%3};"
        : "+f"(c[0]), "+f"(c[1]), "+f"(c[2]), "+f"(c[3])
        : "r"(a[0]), "r"(a[1]), "r"(a[2]), "r"(a[3]), "r"(b[0]), "r"(b[1]));
}
__device__ __forceinline__ void cpa16(uint32_t dst, const void* src) {
    asm volatile("cp.async.ca.shared.global [%0], [%1], 16;" :: "r"(dst), "l"(src));
}
#define CP_COMMIT() asm volatile("cp.async.commit_group;" ::: "memory")
#define CP_WAIT0()  asm volatile("cp.async.wait_group 0;" ::: "memory")

__device__ __forceinline__ uint32_t pack_h2(float a, float b) {
    __half2 t = __floats2half2_rn(a, b);
    return *(uint32_t*)&t;
}
__device__ __forceinline__ float fast_tanh(float q) {
    float r;
    asm("tanh.approx.f32 %0, %1;" : "=f"(r) : "f"(q));
    return r;
}

// ---------------- phase 0: fuse + transpose weights (fp16) -----------------
__global__ void prep_w(const float* __restrict__ W1, const float* __restrict__ W2)
{
    int idx = blockIdx.x * 256 + threadIdx.x;   // idx = k*256 + u
    int k = idx >> 8, u = idx & 255;
    g_WT[u * DD + k] = __float2half_rn(W1[idx] + W2[idx]);
}

// ---------------- phase 1: persistent HMMA GEMM + tanh/v epilogue ----------
// 152 persistent CTAs x 512 threads. W (256x256 fp16) resident in smem.
// Pipelined A staging: STS(chunk i+1) and LDG(chunk i+2) overlap compute(i).
__global__ void __launch_bounds__(512, 1)
score_mma_kernel(const float* __restrict__ X, const float* __restrict__ v)
{
    extern __shared__ char smem[];
    const uint32_t sb = smem_u32(smem);
    const int tid  = threadIdx.x;
    const int wid  = tid >> 5, lane = tid & 31;
    const int wg   = wid >> 3, wn = wid & 7;

    // ---- prologue: W resident load (once) + v
    {
#pragma unroll
        for (int i = 0; i < 16; i++) {
            int u = tid + i * 512;              // 8192 16B-units
            int row = u >> 5, c16 = u & 31;
            cpa16(sb + W_OFF + row * WROWB + c16 * 16,
                  (const char*)(g_WT + (size_t)row * DD) + c16 * 16);
        }
        CP_COMMIT();
    }
    if (tid < 256) ((float*)(smem + SV_OFF))[tid] = v[tid];

    // A assignment: thread -> (row, 16-float segment of 64-k chunk)
    const int ar  = tid >> 2;                   // 0..127
    const int akg = tid & 3;                    // 0..3
    const uint32_t a_rel = (uint32_t)(ar * AROWB + akg * 32);

    // ldmatrix address components
    const uint32_t a_ldm_rel = (uint32_t)(A_OFF + (wg * 64 + (lane & 15)) * AROWB + (lane >> 4) * 16);
    const int nofs  = (lane & 7) + ((lane >> 4) & 1) * 8;
    const int khalf = (lane >> 3) & 1;
    const uint32_t b_ldm_rel0 = (uint32_t)(W_OFF + (wn * 32 + nofs) * WROWB + khalf * 16);

    const float* sv = (const float*)(smem + SV_OFF);
    float* red = (float*)(smem + RED_OFF);

    float c[4][4][4];
#pragma unroll
    for (int i = 0; i < 4; i++)
#pragma unroll
        for (int j = 0; j < 4; j++)
#pragma unroll
            for (int r = 0; r < 4; r++) c[i][j][r] = 0.f;

    int tile  = blockIdx.x;
    int chunk = 0;
    int par   = 0;

    float4 f[4];
    // ---- prologue: stage chunk (tile,0) into buf0; load f = chunk (tile,1)
    {
        const float* ap = X + ((size_t)tile * 128 + ar) * DD + akg * 16;
#pragma unroll
        for (int q = 0; q < 4; q++) f[q] = *(const float4*)(ap + q * 4);
        uint4 h0, h1;
        h0.x = pack_h2(f[0].x, f[0].y); h0.y = pack_h2(f[0].z, f[0].w);
        h0.z = pack_h2(f[1].x, f[1].y); h0.w = pack_h2(f[1].z, f[1].w);
        h1.x = pack_h2(f[2].x, f[2].y); h1.y = pack_h2(f[2].z, f[2].w);
        h1.z = pack_h2(f[3].x, f[3].y); h1.w = pack_h2(f[3].z, f[3].w);
        *(uint4*)(smem + A_OFF + a_rel)      = h0;
        *(uint4*)(smem + A_OFF + a_rel + 16) = h1;
        const float* ap1 = X + ((size_t)tile * 128 + ar) * DD + KC + akg * 16;
#pragma unroll
        for (int q = 0; q < 4; q++) f[q] = *(const float4*)(ap1 + q * 4);
    }
    CP_WAIT0();
    __syncthreads();   // publish W + v + chunk 0

    while (tile < NTILES) {
        // next-chunk indices
        int t1 = tile, c1 = chunk + 1;
        if (c1 == 4) { c1 = 0; t1 += NSM; }

        // 1. stage chunk (t1,c1) from f into the other buffer (overlaps compute)
        if (t1 < NTILES) {
            const uint32_t dst = A_OFF + (uint32_t)(par ^ 1) * ABUF + a_rel;
            uint4 h0, h1;
            h0.x = pack_h2(f[0].x, f[0].y); h0.y = pack_h2(f[0].z, f[0].w);
            h0.z = pack_h2(f[1].x, f[1].y); h0.w = pack_h2(f[1].z, f[1].w);
            h1.x = pack_h2(f[2].x, f[2].y); h1.y = pack_h2(f[2].z, f[2].w);
            h1.z = pack_h2(f[3].x, f[3].y); h1.w = pack_h2(f[3].z, f[3].w);
            *(uint4*)(smem + dst)      = h0;
            *(uint4*)(smem + dst + 16) = h1;
        }

        // 2. LDG chunk (t2,c2) into f
        int t2 = t1, c2 = c1 + 1;
        if (c2 == 4) { c2 = 0; t2 += NSM; }
        if (t2 < NTILES) {
            const float* ap = X + ((size_t)t2 * 128 + ar) * DD + c2 * KC + akg * 16;
#pragma unroll
            for (int q = 0; q < 4; q++) f[q] = *(const float4*)(ap + q * 4);
        }

        // 3. compute 4 k16-steps on chunk (tile,chunk) from buffer 'par'
        const uint32_t abuf = sb + A_OFF + (uint32_t)par * ABUF;
        const uint32_t wkb  = (uint32_t)(chunk * 128);
#pragma unroll
        for (int s = 0; s < 4; s++) {
            uint32_t bh[8];
#pragma unroll
            for (int jp = 0; jp < 2; jp++) {
                uint32_t ba = sb + b_ldm_rel0 + jp * 16 * WROWB + wkb + s * 32;
                ldm4(&bh[jp * 4], ba);
            }
#pragma unroll
            for (int i = 0; i < 4; i++) {
                uint32_t ah[4];
                uint32_t aa = abuf + (a_ldm_rel - A_OFF) + i * 16 * AROWB + s * 32;
                ldm4(ah, aa);
#pragma unroll
                for (int j = 0; j < 4; j++)
                    mma16816(c[i][j], ah, &bh[j * 2]);
            }
        }

        // 4. epilogue at tile end
        if (chunk == 3) {
            float mv0[4], mv1[4];
#pragma unroll
            for (int j = 0; j < 4; j++) {
                int col = wn * 32 + j * 8 + (lane & 3) * 2;
                mv0[j] = sv[col];
                mv1[j] = sv[col + 1];
            }
#pragma unroll
            for (int i = 0; i < 4; i++) {
#pragma unroll
                for (int rh = 0; rh < 2; rh++) {
                    float p = 0.f;
#pragma unroll
                    for (int j = 0; j < 4; j++) {
                        p = fmaf(fast_tanh(c[i][j][rh * 2 + 0]), mv0[j], p);
                        p = fmaf(fast_tanh(c[i][j][rh * 2 + 1]), mv1[j], p);
                    }
                    p += __shfl_xor_sync(0xffffffffu, p, 1);
                    p += __shfl_xor_sync(0xffffffffu, p, 2);
                    if ((lane & 3) == 0)
                        red[(wg * 64 + i * 16 + rh * 8 + (lane >> 2)) * 8 + wn] = p;
                }
            }
            __syncthreads();
            if (tid < 128) {
                float s = 0.f;
#pragma unroll
                for (int w = 0; w < 8; w++) s += red[tid * 8 + w];
                g_scores[(size_t)tile * 128 + tid] = s;
            }
#pragma unroll
            for (int i = 0; i < 4; i++)
#pragma unroll
                for (int j = 0; j < 4; j++)
#pragma unroll
                    for (int r = 0; r < 4; r++) c[i][j][r] = 0.f;
        }

        __syncthreads();   // staged chunk (t1,c1) visible; buffer 'par' reusable
        tile = t1; chunk = c1; par ^= 1;
    }
}

// ---------------- phase 2: softmax over T per batch -------------------------
__global__ void softmax_kernel(float* __restrict__ weights)
{
    const int b   = blockIdx.x;
    const int tid = threadIdx.x;
    const float* s = g_scores + (size_t)b * TT;
    __shared__ float red[256];

    float sc[16];
    float m = -INFINITY;
#pragma unroll
    for (int i = 0; i < 16; i++) {
        sc[i] = s[tid + i * 256];
        m = fmaxf(m, sc[i]);
    }
    red[tid] = m;
    __syncthreads();
    for (int st = 128; st > 0; st >>= 1) {
        if (tid < st) red[tid] = fmaxf(red[tid], red[tid + st]);
        __syncthreads();
    }
    m = red[0];
    __syncthreads();

    float sum = 0.f;
#pragma unroll
    for (int i = 0; i < 16; i++) {
        sc[i] = expf(sc[i] - m);
        sum += sc[i];
    }
    red[tid] = sum;
    __syncthreads();
    for (int st = 128; st > 0; st >>= 1) {
        if (tid < st) red[tid] += red[tid + st];
        __syncthreads();
    }
    const float inv = 1.f / red[0];
#pragma unroll
    for (int i = 0; i < 16; i++)
        weights[(size_t)b * TT + tid + i * 256] = sc[i] * inv;
}

// ---------------- phase 3: context, 2-stage (1024 blocks, float4) ----------
__global__ void __launch_bounds__(256)
ctx_part_kernel(const float* __restrict__ X, const float* __restrict__ w)
{
    const int b   = blockIdx.x;
    const int seg = blockIdx.y;                 // 0..15, 256 timesteps each
    const int q   = threadIdx.x & 63;           // float4 slot over d
    const int tr  = threadIdx.x >> 6;           // 0..3 t-lane
    const float* xb = X + ((size_t)b * TT + seg * 256) * DD + q * 4;
    const float* wb = w + (size_t)b * TT + seg * 256;

    float4 acc = make_float4(0.f, 0.f, 0.f, 0.f);
    for (int it = 0; it < 64; it += 4) {
#pragma unroll
        for (int u2 = 0; u2 < 4; u2++) {
            int t = (it + u2) * 4 + tr;
            float wt = wb[t];
            float4 xv = *(const float4*)(xb + (size_t)t * DD);
            acc.x = fmaf(wt, xv.x, acc.x);
            acc.y = fmaf(wt, xv.y, acc.y);
            acc.z = fmaf(wt, xv.z, acc.z);
            acc.w = fmaf(wt, xv.w, acc.w);
        }
    }

    __shared__ float4 red[256];
    red[threadIdx.x] = acc;
    __syncthreads();
    if (tr == 0) {
        float4 a = red[q], b4 = red[q + 64], c4 = red[q + 128], d4 = red[q + 192];
        float4 r;
        r.x = (a.x + b4.x) + (c4.x + d4.x);
        r.y = (a.y + b4.y) + (c4.y + d4.y);
        r.z = (a.z + b4.z) + (c4.z + d4.z);
        r.w = (a.w + b4.w) + (c4.w + d4.w);
        *(float4*)&g_cpart[((size_t)seg * BB + b) * DD + q * 4] = r;
    }
}

__global__ void ctx_final_kernel(float* __restrict__ ctx)
{
    const int b = blockIdx.x, d = threadIdx.x;
    float s = 0.f;
#pragma unroll
    for (int seg = 0; seg < 16; seg++)
        s += g_cpart[((size_t)seg * BB + b) * DD + d];
    ctx[(size_t)b * DD + d] = s;
}

// ---------------------------------------------------------------------------
extern "C" void kernel_launch(void* const* d_in, const int* in_sizes, int n_in,
                              void* d_out, int out_size)
{
    const float* X  = (const float*)d_in[0];
    const float* W1 = (const float*)d_in[1];
    const float* W2 = (const float*)d_in[2];
    const float* v  = (const float*)d_in[3];

    float* out     = (float*)d_out;
    float* ctx     = out;               // context_vector: B*D floats
    float* weights = out + BB * DD;     // attention_weights: B*T floats

    static int inited = 0;
    if (!inited) {
        cudaFuncSetAttribute(score_mma_kernel,
                             cudaFuncAttributeMaxDynamicSharedMemorySize, SM_TOTAL);
        inited = 1;
    }

    prep_w<<<256, 256>>>(W1, W2);
    score_mma_kernel<<<NSM, 512, SM_TOTAL>>>(X, v);
    softmax_kernel<<<BB, 256>>>(weights);
    ctx_part_kernel<<<dim3(BB, 16), 256>>>(X, weights);
    ctx_final_kernel<<<BB, 256>>>(ctx);
}